// round 10
// baseline (speedup 1.0000x reference)
#include <cuda_runtime.h>
#include <cstdint>

#define B_DIM 512
#define F_DIM 784
#define R_DIM 512
#define C_DIM 16
#define D_DIM 49
#define HALF_LOG_2PI 0.9189385332046727f

// Scratch (allocation-free rule: __device__ global)
__device__ float g_xT[F_DIM * B_DIM];               // [f][b] (1.6MB, L2-resident)

// ---------------------------------------------------------------------------
// packed f32x2 helpers (Blackwell FFMA2 — only reachable via PTX)
// ---------------------------------------------------------------------------
__device__ __forceinline__ unsigned long long fma2(unsigned long long a,
                                                   unsigned long long b,
                                                   unsigned long long c) {
    unsigned long long d;
    asm("fma.rn.f32x2 %0, %1, %2, %3;" : "=l"(d) : "l"(a), "l"(b), "l"(c));
    return d;
}
__device__ __forceinline__ unsigned long long dup2(float v) {   // (v, v)
    unsigned long long r;
    asm("mov.b64 %0, {%1, %1};" : "=l"(r) : "f"(v));
    return r;
}
__device__ __forceinline__ void unpack2(unsigned long long v, float& lo, float& hi) {
    unsigned int l, h;
    asm("mov.b64 {%0, %1}, %2;" : "=r"(l), "=r"(h) : "l"(v));
    lo = __uint_as_float(l);
    hi = __uint_as_float(h);
}
__device__ __forceinline__ uint32_t smem_u32(const void* p) {
    uint32_t a;
    asm("{ .reg .u64 t; cvta.to.shared.u64 t, %1; cvt.u32.u64 %0, t; }" : "=r"(a) : "l"(p));
    return a;
}
__device__ __forceinline__ void cp_async16(uint32_t dst, const void* src) {
    asm volatile("cp.async.cg.shared.global [%0], [%1], 16;" :: "r"(dst), "l"(src));
}

// ---------------------------------------------------------------------------
// Kernel 1: transpose x[b][f] -> xT[f][b].
// ---------------------------------------------------------------------------
__global__ void __launch_bounds__(256) transpose_kernel(const float* __restrict__ x) {
    __shared__ float tile[32][33];
    int fx = blockIdx.x * 32 + threadIdx.x;
    #pragma unroll
    for (int k = 0; k < 32; k += 8) {
        int b = blockIdx.y * 32 + threadIdx.y + k;
        if (fx < F_DIM) tile[threadIdx.y + k][threadIdx.x] = x[b * F_DIM + fx];
    }
    __syncthreads();
    int b_out = blockIdx.y * 32 + threadIdx.x;
    #pragma unroll
    for (int k = 0; k < 32; k += 8) {
        int f = blockIdx.x * 32 + threadIdx.y + k;
        if (f < F_DIM) g_xT[f * B_DIM + b_out] = tile[threadIdx.x][threadIdx.y + k];
    }
}

// ---------------------------------------------------------------------------
// Kernel 2: fused prep + main — crossbar-minimal mapping.
// Block = (r, 256-b half), 128 threads. Thread t owns b = {2t, 2t+1} and
// ALL 16 c (packed as 8 f32x2 c-pairs). Per thread per d:
//   1 LDS.64  : x (all lanes DISTINCT data -> x crosses crossbar once/block)
//   8 LDS.128 : A,B rows — WARP-UNIFORM address (same-addr broadcast = free)
//   2 dup2 (alu) + 32 FFMA2
// Per warp per d: ~384B crossbar vs 64 SMSP-cyc fma -> fma-bound by design.
// acc = 2b x 8 c-pairs = 32 regs. 2 warps/SMSP saturate the fma pipe.
//
// A||B interleaved in one [d][32] smem row: A = floats 0..15, B = 16..31.
// ---------------------------------------------------------------------------
#define XROW 256            // floats per d-row (half of B)
#define ABROW 32            // [d][A(16) || B(16)]
#define DCHUNK 7
#define NCHUNK 7

__global__ void __launch_bounds__(128, 5) main_kernel(const float* __restrict__ loc,
                                                      const float* __restrict__ scale,
                                                      const int* __restrict__ mask,
                                                      float* __restrict__ out) {
    int r   = blockIdx.x;
    int bq0 = blockIdx.y * 256;           // b offset of this half
    int tid = threadIdx.x;

    __shared__ __align__(16) float sAB[D_DIM * ABROW];   // [d][A c0..15, B c0..15]
    __shared__ __align__(16) float xs[2][DCHUNK * XROW];
    __shared__ int   smask[D_DIM];
    __shared__ float sbase[C_DIM];

    // ---- mask first (gather addresses) ----
    if (tid < D_DIM) smask[tid] = mask[r * D_DIM + tid];
    __syncthreads();

    const float* xTp = g_xT;
    uint32_t xs_base[2] = { smem_u32(&xs[0][0]), smem_u32(&xs[1][0]) };

    // ---- chunk 0 gather in flight while we do the coefficient math ----
    for (int i = tid; i < DCHUNK * 64; i += 128) {
        int s = i >> 6, q = i & 63;
        cp_async16(xs_base[0] + (uint32_t)(s * XROW + q * 4) * 4u,
                   xTp + (size_t)smask[s] * B_DIM + bq0 + q * 4);
    }
    asm volatile("cp.async.commit_group;");

    // ---- coefficients: coalesced global reads in native [c][d] order ----
    float* scontrib = &xs[1][0];          // 784 <= 1792 floats; free until chunk 1
    #pragma unroll
    for (int i = tid; i < 784; i += 128) {
        int c = i / D_DIM;
        int d = i - c * D_DIM;
        float lc = loc[r * 784 + i];
        float sc = scale[r * 784 + i];
        float A, Bv, contrib;
        if (sc > 0.0f) {
            float inv = 1.0f / sc;
            float w = inv * inv;
            A = -0.5f * w;
            Bv = w * lc;
            contrib = -0.5f * w * lc * lc - __logf(sc) - HALF_LOG_2PI;
        } else {
            A = 0.0f; Bv = 0.0f; contrib = 0.0f;   // reference zeroes NaN logp
        }
        sAB[d * ABROW + c]      = A;
        sAB[d * ABROW + 16 + c] = Bv;
        scontrib[i] = contrib;            // [c][d] contiguous
    }
    __syncthreads();

    // ---- base[c] reduction: 8 threads per c, shuffle within 8-lane groups ----
    {
        int c = tid >> 3;            // 0..15
        int l = tid & 7;
        float s = 0.0f;
        for (int d = l; d < D_DIM; d += 8) s += scontrib[c * D_DIM + d];
        s += __shfl_down_sync(0xffffffffu, s, 4, 8);
        s += __shfl_down_sync(0xffffffffu, s, 2, 8);
        s += __shfl_down_sync(0xffffffffu, s, 1, 8);
        if (l == 0) sbase[c] = s;
    }
    __syncthreads();    // scontrib reads done -> xs[1] free for chunk 1

    // ---- chunk 1 gather ----
    for (int i = tid; i < DCHUNK * 64; i += 128) {
        int s = i >> 6, q = i & 63;
        cp_async16(xs_base[1] + (uint32_t)(s * XROW + q * 4) * 4u,
                   xTp + (size_t)smask[DCHUNK + s] * B_DIM + bq0 + q * 4);
    }
    asm volatile("cp.async.commit_group;");

    unsigned long long acc[2][8];        // [b][c-pair], 32 regs
    #pragma unroll
    for (int bi = 0; bi < 2; ++bi)
        #pragma unroll
        for (int j = 0; j < 8; ++j) acc[bi][j] = 0ull;

    for (int k = 0; k < NCHUNK; ++k) {
        if (k < NCHUNK - 1) asm volatile("cp.async.wait_group 1;");
        else                asm volatile("cp.async.wait_group 0;");
        __syncthreads();                     // buf[k&1] visible to all

        const float* xb = &xs[k & 1][tid * 2];
        const float* ab = sAB + (k * DCHUNK) * ABROW;

        #pragma unroll
        for (int dd = 0; dd < DCHUNK; ++dd) {
            float2 xv = *reinterpret_cast<const float2*>(xb + dd * XROW);
            const float* row = ab + dd * ABROW;
            ulonglong2 a01 = *reinterpret_cast<const ulonglong2*>(row);       // c0..3
            ulonglong2 a23 = *reinterpret_cast<const ulonglong2*>(row + 4);   // c4..7
            ulonglong2 a45 = *reinterpret_cast<const ulonglong2*>(row + 8);   // c8..11
            ulonglong2 a67 = *reinterpret_cast<const ulonglong2*>(row + 12);  // c12..15
            ulonglong2 b01 = *reinterpret_cast<const ulonglong2*>(row + 16);
            ulonglong2 b23 = *reinterpret_cast<const ulonglong2*>(row + 20);
            ulonglong2 b45 = *reinterpret_cast<const ulonglong2*>(row + 24);
            ulonglong2 b67 = *reinterpret_cast<const ulonglong2*>(row + 28);
            unsigned long long a2[8] = {a01.x, a01.y, a23.x, a23.y,
                                        a45.x, a45.y, a67.x, a67.y};
            unsigned long long b2[8] = {b01.x, b01.y, b23.x, b23.y,
                                        b45.x, b45.y, b67.x, b67.y};
            unsigned long long xd0 = dup2(xv.x);
            unsigned long long xd1 = dup2(xv.y);
            #pragma unroll
            for (int j = 0; j < 8; ++j) {
                unsigned long long t0 = fma2(a2[j], xd0, b2[j]);
                acc[0][j] = fma2(xd0, t0, acc[0][j]);
                unsigned long long t1 = fma2(a2[j], xd1, b2[j]);
                acc[1][j] = fma2(xd1, t1, acc[1][j]);
            }
        }
        __syncthreads();                     // done reading buf[k&1]

        if (k + 2 < NCHUNK) {                // refill buf[k&1] with chunk k+2
            int d0 = (k + 2) * DCHUNK;
            for (int i = tid; i < DCHUNK * 64; i += 128) {
                int s = i >> 6, q = i & 63;
                cp_async16(xs_base[k & 1] + (uint32_t)(s * XROW + q * 4) * 4u,
                           xTp + (size_t)smask[d0 + s] * B_DIM + bq0 + q * 4);
            }
            asm volatile("cp.async.commit_group;");
        }
    }

    // ---- epilogue: each thread writes 2 complete 16-c output rows ----
    float bb[16];
    #pragma unroll
    for (int w = 0; w < 4; ++w) {
        float4 v = *reinterpret_cast<const float4*>(sbase + 4 * w);
        bb[4 * w] = v.x; bb[4 * w + 1] = v.y; bb[4 * w + 2] = v.z; bb[4 * w + 3] = v.w;
    }

    #pragma unroll
    for (int bi = 0; bi < 2; ++bi) {
        float cv[16];
        #pragma unroll
        for (int j = 0; j < 8; ++j) unpack2(acc[bi][j], cv[2 * j], cv[2 * j + 1]);
        size_t rowaddr = (size_t)(bq0 + 2 * tid + bi) * (R_DIM * C_DIM) + r * C_DIM;
        #pragma unroll
        for (int w = 0; w < 4; ++w) {
            float4 o = make_float4(cv[4 * w] + bb[4 * w],
                                   cv[4 * w + 1] + bb[4 * w + 1],
                                   cv[4 * w + 2] + bb[4 * w + 2],
                                   cv[4 * w + 3] + bb[4 * w + 3]);
            *reinterpret_cast<float4*>(out + rowaddr + 4 * w) = o;
        }
    }
}

// ---------------------------------------------------------------------------
extern "C" void kernel_launch(void* const* d_in, const int* in_sizes, int n_in,
                              void* d_out, int out_size) {
    const float* x     = (const float*)d_in[0];
    const int*   mask  = (const int*)d_in[1];
    const float* loc   = (const float*)d_in[2];
    const float* scale = (const float*)d_in[3];
    float* out = (float*)d_out;

    transpose_kernel<<<dim3((F_DIM + 31) / 32, B_DIM / 32), dim3(32, 8)>>>(x);
    main_kernel<<<dim3(R_DIM, 2), 128>>>(loc, scale, mask, out);
}

// round 11
// speedup vs baseline: 1.7739x; 1.7739x over previous
#include <cuda_runtime.h>
#include <cstdint>

#define B_DIM 512
#define F_DIM 784
#define R_DIM 512
#define C_DIM 16
#define D_DIM 49
#define HALF_LOG_2PI 0.9189385332046727f

// Scratch (allocation-free rule: __device__ global)
__device__ float g_xT[F_DIM * B_DIM];               // [f][b] (1.6MB, L2-resident)

// ---------------------------------------------------------------------------
// packed f32x2 helpers (Blackwell FFMA2 — only reachable via PTX)
// ---------------------------------------------------------------------------
__device__ __forceinline__ unsigned long long fma2(unsigned long long a,
                                                   unsigned long long b,
                                                   unsigned long long c) {
    unsigned long long d;
    asm("fma.rn.f32x2 %0, %1, %2, %3;" : "=l"(d) : "l"(a), "l"(b), "l"(c));
    return d;
}
__device__ __forceinline__ unsigned long long dup2(float v) {   // (v, v)
    unsigned long long r;
    asm("mov.b64 %0, {%1, %1};" : "=l"(r) : "f"(v));
    return r;
}
__device__ __forceinline__ void unpack2(unsigned long long v, float& lo, float& hi) {
    unsigned int l, h;
    asm("mov.b64 {%0, %1}, %2;" : "=r"(l), "=r"(h) : "l"(v));
    lo = __uint_as_float(l);
    hi = __uint_as_float(h);
}
__device__ __forceinline__ uint32_t smem_u32(const void* p) {
    uint32_t a;
    asm("{ .reg .u64 t; cvta.to.shared.u64 t, %1; cvt.u32.u64 %0, t; }" : "=r"(a) : "l"(p));
    return a;
}
__device__ __forceinline__ void cp_async16(uint32_t dst, const void* src) {
    asm volatile("cp.async.cg.shared.global [%0], [%1], 16;" :: "r"(dst), "l"(src));
}

// ---------------------------------------------------------------------------
// Kernel 1: transpose x[b][f] -> xT[f][b].
// ---------------------------------------------------------------------------
__global__ void __launch_bounds__(256) transpose_kernel(const float* __restrict__ x) {
    __shared__ float tile[32][33];
    int fx = blockIdx.x * 32 + threadIdx.x;
    #pragma unroll
    for (int k = 0; k < 32; k += 8) {
        int b = blockIdx.y * 32 + threadIdx.y + k;
        if (fx < F_DIM) tile[threadIdx.y + k][threadIdx.x] = x[b * F_DIM + fx];
    }
    __syncthreads();
    int b_out = blockIdx.y * 32 + threadIdx.x;
    #pragma unroll
    for (int k = 0; k < 32; k += 8) {
        int f = blockIdx.x * 32 + threadIdx.y + k;
        if (f < F_DIM) g_xT[f * B_DIM + b_out] = tile[threadIdx.x][threadIdx.y + k];
    }
}

// ---------------------------------------------------------------------------
// Kernel 2: fused prep + main (R9 mapping + 3-stage pipeline).
// Block = (r, 256-b half), 128 threads, thread tile 8b x 4c with f32x2
// lanes = (c, c+1): A/B un-duplicated ([d][16] rows), x scalar + dup2 (alu).
// Per thread per d: 4 LDS.128 + 8 dup2 + 32 FFMA2.
//
// Pipeline: 3 smem buffers, chunk k+2 issued at END of iteration k ->
// ONE __syncthreads per chunk (top barrier of iter k proves all warps are
// past chunk k-1, the last reader of the buffer being refilled), and
// prefetch distance ~2 chunk-times >> L2 latency.
// ---------------------------------------------------------------------------
#define XROW 256            // floats per d-row (half of B)
#define ABROW 16            // [d][16 c] rows
#define DCHUNK 7
#define NCHUNK 7
#define NBUF 3

__global__ void __launch_bounds__(128, 7) main_kernel(const float* __restrict__ loc,
                                                      const float* __restrict__ scale,
                                                      const int* __restrict__ mask,
                                                      float* __restrict__ out) {
    int r   = blockIdx.x;
    int bq0 = blockIdx.y * 256;           // b offset of this half
    int tid = threadIdx.x;

    __shared__ __align__(16) float sA[D_DIM * ABROW];    // [d][c], -0.5/s^2
    __shared__ __align__(16) float sB[D_DIM * ABROW];    // [d][c], loc/s^2
    __shared__ __align__(16) float xs[NBUF][DCHUNK * XROW];
    __shared__ int   smask[D_DIM];
    __shared__ float sbase[C_DIM];

    // ---- mask first (gather addresses) ----
    if (tid < D_DIM) smask[tid] = mask[r * D_DIM + tid];
    __syncthreads();

    const float* xTp = g_xT;
    uint32_t xs_base[NBUF] = { smem_u32(&xs[0][0]), smem_u32(&xs[1][0]),
                               smem_u32(&xs[2][0]) };

    // ---- chunks 0 and 1 in flight while we do the coefficient math ----
    for (int i = tid; i < DCHUNK * 64; i += 128) {
        int s = i >> 6, q = i & 63;
        cp_async16(xs_base[0] + (uint32_t)(s * XROW + q * 4) * 4u,
                   xTp + (size_t)smask[s] * B_DIM + bq0 + q * 4);
    }
    asm volatile("cp.async.commit_group;");
    for (int i = tid; i < DCHUNK * 64; i += 128) {
        int s = i >> 6, q = i & 63;
        cp_async16(xs_base[1] + (uint32_t)(s * XROW + q * 4) * 4u,
                   xTp + (size_t)smask[DCHUNK + s] * B_DIM + bq0 + q * 4);
    }
    asm volatile("cp.async.commit_group;");

    // ---- coefficients: coalesced global reads in native [c][d] order ----
    float* scontrib = &xs[2][0];          // 784 <= 1792 floats; free until chunk 2
    #pragma unroll
    for (int i = tid; i < 784; i += 128) {
        int c = i / D_DIM;
        int d = i - c * D_DIM;
        float lc = loc[r * 784 + i];
        float sc = scale[r * 784 + i];
        float A, Bv, contrib;
        if (sc > 0.0f) {
            float inv = 1.0f / sc;
            float w = inv * inv;
            A = -0.5f * w;
            Bv = w * lc;
            contrib = -0.5f * w * lc * lc - __logf(sc) - HALF_LOG_2PI;
        } else {
            A = 0.0f; Bv = 0.0f; contrib = 0.0f;   // reference zeroes NaN logp
        }
        sA[d * ABROW + c] = A;
        sB[d * ABROW + c] = Bv;
        scontrib[i] = contrib;            // [c][d] contiguous
    }
    __syncthreads();

    // ---- base[c] reduction: 8 threads per c, shuffle within 8-lane groups ----
    {
        int c = tid >> 3;            // 0..15
        int l = tid & 7;
        float s = 0.0f;
        for (int d = l; d < D_DIM; d += 8) s += scontrib[c * D_DIM + d];
        s += __shfl_down_sync(0xffffffffu, s, 4, 8);
        s += __shfl_down_sync(0xffffffffu, s, 2, 8);
        s += __shfl_down_sync(0xffffffffu, s, 1, 8);
        if (l == 0) sbase[c] = s;
    }
    // NOTE: no barrier needed here before the loop: iter-0's top barrier
    // orders scontrib reads (all warps) before chunk 2's refill of xs[2],
    // which is issued at the END of iter 0.

    int g = tid >> 2;    // 0..31 -> b positions g*4+{0..3} and 128+g*4+{0..3}
    int h = tid & 3;     // 0..3  -> c group 4h..4h+3

    unsigned long long acc[8][2];        // [b][c-pair], 32 regs
    #pragma unroll
    for (int p = 0; p < 8; ++p) { acc[p][0] = 0ull; acc[p][1] = 0ull; }

    for (int k = 0; k < NCHUNK; ++k) {
        // chunk k is the oldest pending group; allow the newest (k+1) to fly
        if (k < NCHUNK - 1) asm volatile("cp.async.wait_group 1;");
        else                asm volatile("cp.async.wait_group 0;");
        __syncthreads();                     // buf[k%3] visible; all warps past k-1

        int buf = k % NBUF;
        const float* xb = &xs[buf][g * 4];
        const float* Ab = sA + k * (DCHUNK * ABROW) + h * 4;
        const float* Bb = sB + k * (DCHUNK * ABROW) + h * 4;

        #pragma unroll
        for (int dd = 0; dd < DCHUNK; ++dd) {
            const float* xr = xb + dd * XROW;
            float4 xv0 = *reinterpret_cast<const float4*>(xr);         // b = g*4+..
            float4 xv1 = *reinterpret_cast<const float4*>(xr + 128);   // b = 128+g*4+..
            ulonglong2 av = *reinterpret_cast<const ulonglong2*>(Ab + dd * ABROW);
            ulonglong2 bv = *reinterpret_cast<const ulonglong2*>(Bb + dd * ABROW);
            float xf[8] = {xv0.x, xv0.y, xv0.z, xv0.w, xv1.x, xv1.y, xv1.z, xv1.w};
            unsigned long long a2[2] = {av.x, av.y};
            unsigned long long b2[2] = {bv.x, bv.y};
            #pragma unroll
            for (int p = 0; p < 8; ++p) {
                unsigned long long xd = dup2(xf[p]);    // alu pipe (idle)
                #pragma unroll
                for (int j = 0; j < 2; ++j) {
                    unsigned long long t = fma2(a2[j], xd, b2[j]);
                    acc[p][j] = fma2(xd, t, acc[p][j]);
                }
            }
        }

        if (k + 2 < NCHUNK) {                // refill buf[(k+2)%3] with chunk k+2
            int d0 = (k + 2) * DCHUNK;
            int tb = (k + 2) % NBUF;         // last read at iter k-1 -> safe
            for (int i = tid; i < DCHUNK * 64; i += 128) {
                int s = i >> 6, q = i & 63;
                cp_async16(xs_base[tb] + (uint32_t)(s * XROW + q * 4) * 4u,
                           xTp + (size_t)smask[d0 + s] * B_DIM + bq0 + q * 4);
            }
            asm volatile("cp.async.commit_group;");
        }
    }

    // ---- epilogue: unpack c-pairs, add base, store one float4 per b ----
    float bb0 = sbase[4 * h];
    float bb1 = sbase[4 * h + 1];
    float bb2 = sbase[4 * h + 2];
    float bb3 = sbase[4 * h + 3];

    #pragma unroll
    for (int p = 0; p < 8; ++p) {
        int bl = (p < 4) ? (g * 4 + p) : (128 + g * 4 + (p - 4));
        float c0, c1, c2, c3;
        unpack2(acc[p][0], c0, c1);
        unpack2(acc[p][1], c2, c3);
        float4 o = make_float4(c0 + bb0, c1 + bb1, c2 + bb2, c3 + bb3);
        *reinterpret_cast<float4*>(out + (size_t)(bq0 + bl) * (R_DIM * C_DIM)
                                   + r * C_DIM + 4 * h) = o;
    }
}

// ---------------------------------------------------------------------------
extern "C" void kernel_launch(void* const* d_in, const int* in_sizes, int n_in,
                              void* d_out, int out_size) {
    const float* x     = (const float*)d_in[0];
    const int*   mask  = (const int*)d_in[1];
    const float* loc   = (const float*)d_in[2];
    const float* scale = (const float*)d_in[3];
    float* out = (float*)d_out;

    transpose_kernel<<<dim3((F_DIM + 31) / 32, B_DIM / 32), dim3(32, 8)>>>(x);
    main_kernel<<<dim3(R_DIM, 2), 128>>>(loc, scale, mask, out);
}